// round 4
// baseline (speedup 1.0000x reference)
#include <cuda_runtime.h>
#include <math.h>

// ---------------- problem constants ----------------
#define BSZ 256
#define SSZ 100
#define ISZ 128
#define HSZ 1024
#define OSZ 128
#define LSZ 2
#define USZ 1344
#define KSZ 4
#define MR  (BSZ*SSZ)      // 25600 rows
#define G4H (4*HSZ)        // 4096

// ---------------- device scratch (no runtime allocation allowed) ----------------
__device__ float g_h [MR*HSZ];
__device__ float g_xn[MR*HSZ];
__device__ float g_xc[MR*HSZ];
__device__ float g_ys[MR*HSZ];
__device__ float g_wx[(size_t)MR*G4H];
__device__ float g_ff1[(size_t)MR*2*USZ];
__device__ float g_ff2[(size_t)MR*USZ];
__device__ float g_raw[BSZ*G4H];
__device__ float g_Y[BSZ*HSZ];
__device__ float g_C[BSZ*HSZ];
__device__ float g_N[BSZ*HSZ];
__device__ float g_M[BSZ*HSZ];

// ---------------- double-buffered tiled SGEMM ----------------
// C[m,n] = sum_k A[m,k] * B'[k,n]  (+bias[n]) (+D[m,n]) (+=C if accum)
// TRANSB=true : B is [N,K] row-major (weight matrices, "NT")
// TRANSB=false: B is [K,N] row-major (recurrent R, "NN")
template<int BM,int BN,int BK,int TM,int TN,bool TRANSB>
__global__ void sgemm(const float* __restrict__ A, const float* __restrict__ Bm,
                      float* __restrict__ C,
                      int K, int lda, int ldb, int ldc,
                      const float* __restrict__ bias,
                      const float* __restrict__ D, int ldd,
                      int accum)
{
    constexpr int THREADS = (BM/TM)*(BN/TN);
    constexpr int ALD = (BM*BK)/(THREADS*4);
    constexpr int BLD = (BN*BK)/(THREADS*4);
    static_assert((BM*BK) % (THREADS*4) == 0, "A tile load");
    static_assert((BN*BK) % (THREADS*4) == 0, "B tile load");
    __shared__ float As[2][BK][BM];
    __shared__ float Bs[2][BK][BN];
    const int tid = threadIdx.x;
    const int m0 = blockIdx.y * BM;
    const int n0 = blockIdx.x * BN;
    const int tr = tid / (BN/TN);
    const int tc = tid % (BN/TN);
    float acc[TM][TN] = {};

    // tile loader: global -> smem stage s at k-offset k0
    auto load_tiles = [&](int k0, int s) {
        #pragma unroll
        for (int i = 0; i < ALD; i++) {
            int idx = (tid + i*THREADS)*4;
            int m = idx / BK, kk = idx % BK;
            float4 v = *reinterpret_cast<const float4*>(A + (size_t)(m0+m)*lda + k0 + kk);
            As[s][kk+0][m]=v.x; As[s][kk+1][m]=v.y; As[s][kk+2][m]=v.z; As[s][kk+3][m]=v.w;
        }
        #pragma unroll
        for (int i = 0; i < BLD; i++) {
            int idx = (tid + i*THREADS)*4;
            if (TRANSB) {
                int n = idx / BK, kk = idx % BK;
                float4 v = *reinterpret_cast<const float4*>(Bm + (size_t)(n0+n)*ldb + k0 + kk);
                Bs[s][kk+0][n]=v.x; Bs[s][kk+1][n]=v.y; Bs[s][kk+2][n]=v.z; Bs[s][kk+3][n]=v.w;
            } else {
                int kk = idx / BN, n = idx % BN;
                *reinterpret_cast<float4*>(&Bs[s][kk][n]) =
                    *reinterpret_cast<const float4*>(Bm + (size_t)(k0+kk)*ldb + n0 + n);
            }
        }
    };

    load_tiles(0, 0);
    __syncthreads();
    int cur = 0;
    for (int k0 = BK; k0 < K + BK; k0 += BK) {
        int nxt = cur ^ 1;
        if (k0 < K) load_tiles(k0, nxt);       // overlap with compute below
        #pragma unroll
        for (int kk = 0; kk < BK; kk++) {
            float ar[TM], br[TN];
            #pragma unroll
            for (int i = 0; i < TM; i++) ar[i] = As[cur][kk][tr*TM + i];
            #pragma unroll
            for (int j = 0; j < TN; j++) br[j] = Bs[cur][kk][tc*TN + j];
            #pragma unroll
            for (int i = 0; i < TM; i++)
                #pragma unroll
                for (int j = 0; j < TN; j++)
                    acc[i][j] += ar[i]*br[j];
        }
        __syncthreads();
        cur = nxt;
    }

    #pragma unroll
    for (int i = 0; i < TM; i++) {
        int m = m0 + tr*TM + i;
        #pragma unroll
        for (int j = 0; j < TN; j++) {
            int n = n0 + tc*TN + j;
            float v = acc[i][j];
            if (bias) v += bias[n];
            if (D)    v += D[(size_t)m*ldd + n];
            size_t off = (size_t)m*ldc + n;
            if (accum) v += C[off];
            C[off] = v;
        }
    }
}

// ---------------- block reduce ----------------
__device__ __forceinline__ float blockReduceSum(float v) {
    __shared__ float sred[32];
    __syncthreads();                       // guard reuse across calls
    int lane = threadIdx.x & 31, w = threadIdx.x >> 5;
    #pragma unroll
    for (int o = 16; o > 0; o >>= 1) v += __shfl_down_sync(0xffffffffu, v, o);
    if (lane == 0) sred[w] = v;
    __syncthreads();
    int nw = blockDim.x >> 5;
    v = (threadIdx.x < nw) ? sred[threadIdx.x] : 0.f;
    if (w == 0) {
        #pragma unroll
        for (int o = 16; o > 0; o >>= 1) v += __shfl_down_sync(0xffffffffu, v, o);
        if (lane == 0) sred[0] = v;
    }
    __syncthreads();
    return sred[0];
}

// ---------------- LayerNorm (weight only, eps=1e-5), 256 threads, H=1024 ----------------
__global__ void ln_k(const float* __restrict__ in, const float* __restrict__ w,
                     float* __restrict__ out) {
    size_t row = blockIdx.x;
    float4 x = reinterpret_cast<const float4*>(in + row*HSZ)[threadIdx.x];
    float s = x.x + x.y + x.z + x.w;
    s = blockReduceSum(s);
    float mu = s * (1.f/HSZ);
    float dx = x.x-mu, dy = x.y-mu, dz = x.z-mu, dw = x.w-mu;
    float vs = dx*dx + dy*dy + dz*dz + dw*dw;
    vs = blockReduceSum(vs);
    float r = rsqrtf(vs*(1.f/HSZ) + 1e-5f);
    float4 wv = reinterpret_cast<const float4*>(w)[threadIdx.x];
    float4 o = make_float4(dx*r*wv.x, dy*r*wv.y, dz*r*wv.z, dw*r*wv.w);
    reinterpret_cast<float4*>(out + row*HSZ)[threadIdx.x] = o;
}

// h += LN(ys) * w
__global__ void add_ln_k(const float* __restrict__ ys, const float* __restrict__ w,
                         float* __restrict__ h) {
    size_t row = blockIdx.x;
    float4 x = reinterpret_cast<const float4*>(ys + row*HSZ)[threadIdx.x];
    float s = x.x + x.y + x.z + x.w;
    s = blockReduceSum(s);
    float mu = s * (1.f/HSZ);
    float dx = x.x-mu, dy = x.y-mu, dz = x.z-mu, dw = x.w-mu;
    float vs = dx*dx + dy*dy + dz*dz + dw*dw;
    vs = blockReduceSum(vs);
    float r = rsqrtf(vs*(1.f/HSZ) + 1e-5f);
    float4 wv = reinterpret_cast<const float4*>(w)[threadIdx.x];
    float4 hv = reinterpret_cast<float4*>(h + row*HSZ)[threadIdx.x];
    hv.x += dx*r*wv.x; hv.y += dy*r*wv.y; hv.z += dz*r*wv.z; hv.w += dw*r*wv.w;
    reinterpret_cast<float4*>(h + row*HSZ)[threadIdx.x] = hv;
}

// ---------------- depthwise causal conv (K=4) + SiLU ----------------
__global__ void conv_silu_k(const float* __restrict__ xn, const float* __restrict__ cw,
                            const float* __restrict__ cb, float* __restrict__ xc) {
    size_t idx = (size_t)blockIdx.x*blockDim.x + threadIdx.x;   // < MR*H
    int h = (int)(idx % HSZ);
    size_t bs = idx / HSZ;
    int s = (int)(bs % SSZ);
    float acc = cb[h];
    #pragma unroll
    for (int k = 0; k < KSZ; k++) {
        int s2 = s - (KSZ-1) + k;
        if (s2 >= 0) {
            ptrdiff_t off = (ptrdiff_t)(s2 - s) * HSZ;
            acc += xn[(ptrdiff_t)idx + off] * cw[h*KSZ + k];
        }
    }
    xc[idx] = acc / (1.f + expf(-acc));   // silu
}

// ---------------- sLSTM gate pointwise step ----------------
__global__ void gate_k(const float* __restrict__ raw, const float* __restrict__ cb,
                       float* __restrict__ Y, float* __restrict__ Cc,
                       float* __restrict__ Nn, float* __restrict__ Mm,
                       float* __restrict__ ys, int t) {
    int idx = blockIdx.x*blockDim.x + threadIdx.x;   // < B*H
    int b = idx >> 10, h = idx & 1023;
    const float* rr = raw + (size_t)b*G4H;
    float ir  = rr[h]          + cb[h];
    float fr  = rr[HSZ + h]    + cb[HSZ + h];
    float zr  = rr[2*HSZ + h]  + cb[2*HSZ + h];
    float orr = rr[3*HSZ + h]  + cb[3*HSZ + h];
    float m = Mm[idx], c = Cc[idx], n = Nn[idx];
    float ls = (fr >= 0.f) ? -log1pf(expf(-fr)) : (fr - log1pf(expf(fr)));  // log_sigmoid
    float lfm = m + ls;
    float mn = (n == 0.f) ? ir : fmaxf(ir, lfm);
    float ig = expf(ir - mn);
    float fg = expf(lfm - mn);
    float cn = fg*c + ig*tanhf(zr);
    float nn2 = fg*n + ig;
    float yv = (1.f/(1.f + expf(-orr))) * cn / nn2;
    Mm[idx] = mn; Cc[idx] = cn; Nn[idx] = nn2; Y[idx] = yv;
    ys[((size_t)b*SSZ + t)*HSZ + h] = yv;
}

__global__ void zero_states_k(float* __restrict__ Y, float* __restrict__ C,
                              float* __restrict__ N, float* __restrict__ M) {
    int idx = blockIdx.x*blockDim.x + threadIdx.x;
    Y[idx] = 0.f; C[idx] = 0.f; N[idx] = 0.f; M[idx] = 0.f;
}

// ---------------- gated GELU (exact) ----------------
__global__ void act_k(const float* __restrict__ ff1, float* __restrict__ ff2) {
    size_t idx = (size_t)blockIdx.x*blockDim.x + threadIdx.x;   // < MR*U
    size_t m = idx / USZ;
    int u = (int)(idx % USZ);
    const float* r = ff1 + m*(2*USZ);
    float g = r[u], v = r[USZ + u];
    float ge = 0.5f * g * (1.f + erff(g * 0.70710678118654752440f));
    ff2[idx] = ge * v;
}

// ---------------- final LN + FC on last position ----------------
__global__ void final_k(const float* __restrict__ hbuf, const float* __restrict__ pw,
                        const float* __restrict__ fw, const float* __restrict__ fb,
                        float* __restrict__ out) {
    __shared__ float sh[HSZ];
    int b = blockIdx.x, tid = threadIdx.x;   // 128 threads
    const float* row = hbuf + ((size_t)b*SSZ + SSZ - 1)*HSZ;
    float lv[8];
    float s = 0.f;
    #pragma unroll
    for (int i = 0; i < 8; i++) { lv[i] = row[tid*8 + i]; s += lv[i]; }
    s = blockReduceSum(s);
    float mu = s * (1.f/HSZ);
    float vs = 0.f;
    #pragma unroll
    for (int i = 0; i < 8; i++) { lv[i] -= mu; vs += lv[i]*lv[i]; }
    vs = blockReduceSum(vs);
    float r = rsqrtf(vs*(1.f/HSZ) + 1e-5f);
    #pragma unroll
    for (int i = 0; i < 8; i++) sh[tid*8 + i] = lv[i]*r*pw[tid*8 + i];
    __syncthreads();
    float acc = fb[tid];
    const float* wrow = fw + (size_t)tid*HSZ;
    #pragma unroll 4
    for (int k = 0; k < HSZ; k += 4) {
        float4 wv = *reinterpret_cast<const float4*>(wrow + k);
        acc += sh[k]*wv.x + sh[k+1]*wv.y + sh[k+2]*wv.z + sh[k+3]*wv.w;
    }
    out[b*OSZ + tid] = acc;
}

// ---------------- host ----------------
template <typename T>
static float* sym_addr(const T& sym) {
    void* p = nullptr;
    cudaGetSymbolAddress(&p, sym);
    return (float*)p;
}

extern "C" void kernel_launch(void* const* d_in, const int* in_sizes, int n_in,
                              void* d_out, int out_size) {
    (void)in_sizes; (void)n_in; (void)out_size;
    const float* x      = (const float*)d_in[0];
    const float* emb_w  = (const float*)d_in[1];
    const float* emb_b  = (const float*)d_in[2];
    const float* conv_w = (const float*)d_in[3];
    const float* conv_b = (const float*)d_in[4];
    const float* Wi     = (const float*)d_in[5];
    const float* Wf     = (const float*)d_in[6];
    const float* Wz     = (const float*)d_in[7];
    const float* Wo     = (const float*)d_in[8];
    const float* R      = (const float*)d_in[9];
    const float* cell_b = (const float*)d_in[10];
    const float* gn_w   = (const float*)d_in[11];
    const float* ln1_w  = (const float*)d_in[12];
    const float* ln2_w  = (const float*)d_in[13];
    const float* ff_up  = (const float*)d_in[14];
    const float* ff_down= (const float*)d_in[15];
    const float* post_w = (const float*)d_in[16];
    const float* fc_w   = (const float*)d_in[17];
    const float* fc_b   = (const float*)d_in[18];
    float* out = (float*)d_out;

    float* h   = sym_addr(g_h);
    float* xn  = sym_addr(g_xn);
    float* xc  = sym_addr(g_xc);
    float* ys  = sym_addr(g_ys);
    float* wx  = sym_addr(g_wx);
    float* ff1 = sym_addr(g_ff1);
    float* ff2 = sym_addr(g_ff2);
    float* raw = sym_addr(g_raw);
    float* Yp  = sym_addr(g_Y);
    float* Cp  = sym_addr(g_C);
    float* Np  = sym_addr(g_N);
    float* Mp  = sym_addr(g_M);

    // h = x @ emb_w.T + emb_b   [25600,128]x[1024,128]^T
    sgemm<128,128,16,8,8,true><<<dim3(HSZ/128, MR/128), 256>>>(
        x, emb_w, h, ISZ, ISZ, ISZ, HSZ, emb_b, nullptr, 0, 0);

    for (int l = 0; l < LSZ; l++) {
        const float* Wl[4] = { Wi + (size_t)l*HSZ*HSZ, Wf + (size_t)l*HSZ*HSZ,
                               Wz + (size_t)l*HSZ*HSZ, Wo + (size_t)l*HSZ*HSZ };
        // xn = LN(h)*ln1_w
        ln_k<<<MR, 256>>>(h, ln1_w + l*HSZ, xn);
        // xc = silu(causal_conv(xn))
        conv_silu_k<<<(MR*HSZ)/256, 256>>>(xn, conv_w + (size_t)l*HSZ*KSZ,
                                           conv_b + l*HSZ, xc);
        // Wx gates: [i,f] from xc, [z,o] from xn
        for (int g = 0; g < 4; g++) {
            const float* Amat = (g < 2) ? xc : xn;
            sgemm<128,128,16,8,8,true><<<dim3(HSZ/128, MR/128), 256>>>(
                Amat, Wl[g], wx + g*HSZ, HSZ, HSZ, HSZ, G4H, nullptr, nullptr, 0, 0);
        }
        // recurrence
        zero_states_k<<<(BSZ*HSZ)/256, 256>>>(Yp, Cp, Np, Mp);
        const float* Rl = R + (size_t)l*HSZ*G4H;
        const float* cbl = cell_b + l*G4H;
        for (int t = 0; t < SSZ; t++) {
            // raw = Y @ R + Wx[:,t,:]
            sgemm<64,128,16,4,8,false><<<dim3(G4H/128, BSZ/64), 256>>>(
                Yp, Rl, raw, HSZ, HSZ, G4H, G4H, nullptr,
                wx + (size_t)t*G4H, SSZ*G4H, 0);
            gate_k<<<(BSZ*HSZ)/256, 256>>>(raw, cbl, Yp, Cp, Np, Mp, ys, t);
        }
        // h += LN(ys)*gn_w
        add_ln_k<<<MR, 256>>>(ys, gn_w + l*HSZ, h);
        // FFN
        ln_k<<<MR, 256>>>(h, ln2_w + l*HSZ, xn);
        sgemm<128,128,16,8,8,true><<<dim3((2*USZ)/128, MR/128), 256>>>(
            xn, ff_up + (size_t)l*2*USZ*HSZ, ff1, HSZ, HSZ, HSZ, 2*USZ,
            nullptr, nullptr, 0, 0);
        act_k<<<((size_t)MR*USZ)/256, 256>>>(ff1, ff2);
        sgemm<128,128,16,8,8,true><<<dim3(HSZ/128, MR/128), 256>>>(
            ff2, ff_down + (size_t)l*HSZ*USZ, h, USZ, USZ, USZ, HSZ,
            nullptr, nullptr, 0, 1);
    }
    final_k<<<BSZ, 128>>>(h, post_w, fc_w, fc_b, out);
}

// round 16
// speedup vs baseline: 2.4795x; 2.4795x over previous
#include <cuda_runtime.h>
#include <math.h>
#include <stdint.h>

// ---------------- problem constants ----------------
#define BSZ 256
#define SSZ 100
#define ISZ 128
#define HSZ 1024
#define OSZ 128
#define LSZ 2
#define USZ 1344
#define KSZ 4
#define MR  (BSZ*SSZ)      // 25600 rows
#define G4H (4*HSZ)        // 4096

// ---------------- device scratch (no runtime allocation allowed) ----------------
__device__ float g_h [MR*HSZ];
__device__ float g_xn[MR*HSZ];
__device__ float g_xc[MR*HSZ];
__device__ float g_ys[MR*HSZ];
__device__ float g_wx[(size_t)MR*G4H];
__device__ float g_ff1[(size_t)MR*2*USZ];
__device__ float g_ff2[(size_t)MR*USZ];
__device__ float g_raw[BSZ*G4H];
__device__ float g_RT [(size_t)G4H*HSZ];   // R^T for current layer (4096 x 1024)
__device__ float g_Y[BSZ*HSZ];             // zero input for step t=0 only
__device__ float g_C[BSZ*HSZ];
__device__ float g_N[BSZ*HSZ];
__device__ float g_M[BSZ*HSZ];

// ---------------- tf32 helpers ----------------
__device__ __forceinline__ unsigned f2tf(float f) {
    unsigned u;
    asm("cvt.rna.tf32.f32 %0, %1;" : "=r"(u) : "f"(f));
    return u;
}

__device__ __forceinline__ void mma_tf32(float c[4], const unsigned a[4], const unsigned b[2]) {
    asm volatile(
        "mma.sync.aligned.m16n8k8.row.col.f32.tf32.tf32.f32 "
        "{%0,%1,%2,%3}, {%4,%5,%6,%7}, {%8,%9}, {%0,%1,%2,%3};"
        : "+f"(c[0]), "+f"(c[1]), "+f"(c[2]), "+f"(c[3])
        : "r"(a[0]), "r"(a[1]), "r"(a[2]), "r"(a[3]), "r"(b[0]), "r"(b[1]));
}

// ---------------- tf32 tensor-core GEMM (NT: B is [N,K] row-major) ----------------
// C[m,n] = sum_k A[m,k]*B[n,k]  (+bias[n]) (+D[m,n]) (+=C if accum)
// BM = MI*32, BN=128, BK=16, 256 threads, 8 warps (2 m x 4 n), warp tile (MI*16)x32.
#define TG_BN 128
#define TG_BK 16
#define TG_PK 20   // padded k stride: 16+4 -> conflict-free fragment loads

template<int MI>   // m16 tiles per warp; BM = MI*32
__global__ __launch_bounds__(256)
void tgemm(const float* __restrict__ A, const float* __restrict__ Bm,
           float* __restrict__ C,
           int K, int lda, int ldb, int ldc,
           const float* __restrict__ bias,
           const float* __restrict__ D, int ldd,
           int accum)
{
    constexpr int BM = MI * 32;
    constexpr int ALD = (BM * TG_BK) / (256 * 4);   // A-stage fill iterations
    __shared__ __align__(16) unsigned As[2][BM][TG_PK];
    __shared__ __align__(16) unsigned Bs[2][TG_BN][TG_PK];

    const int tid  = threadIdx.x;
    const int wid  = tid >> 5;
    const int lane = tid & 31;
    const int gid  = lane >> 2;      // 0..7
    const int tg   = lane & 3;       // 0..3
    const int m0 = blockIdx.y * BM;
    const int n0 = blockIdx.x * TG_BN;
    const int wm0 = (wid >> 2) * (MI * 16); // warp m offset within tile
    const int wn0 = (wid & 3) * 32;         // warp n offset within tile

    float acc[MI][4][4];
    #pragma unroll
    for (int i = 0; i < MI; i++)
        #pragma unroll
        for (int j = 0; j < 4; j++)
            #pragma unroll
            for (int r = 0; r < 4; r++) acc[i][j][r] = 0.f;

    // fill one stage: global float4 -> tf32 -> STS.128 (k-inner layout)
    auto load_tiles = [&](int k0, int s) {
        #pragma unroll
        for (int i = 0; i < ALD; i++) {
            int idx = (tid + i*256) * 4;
            int m = idx / TG_BK, kk = idx % TG_BK;
            float4 v = *reinterpret_cast<const float4*>(A + (size_t)(m0+m)*lda + k0 + kk);
            uint4 t = make_uint4(f2tf(v.x), f2tf(v.y), f2tf(v.z), f2tf(v.w));
            *reinterpret_cast<uint4*>(&As[s][m][kk]) = t;
        }
        #pragma unroll
        for (int i = 0; i < 2; i++) {              // BN*BK/(256*4) = 2
            int idx = (tid + i*256) * 4;
            int n = idx / TG_BK, kk = idx % TG_BK;
            float4 v = *reinterpret_cast<const float4*>(Bm + (size_t)(n0+n)*ldb + k0 + kk);
            uint4 t = make_uint4(f2tf(v.x), f2tf(v.y), f2tf(v.z), f2tf(v.w));
            *reinterpret_cast<uint4*>(&Bs[s][n][kk]) = t;
        }
    };

    load_tiles(0, 0);
    __syncthreads();
    int cur = 0;
    for (int k0 = TG_BK; k0 < K + TG_BK; k0 += TG_BK) {
        int nxt = cur ^ 1;
        if (k0 < K) load_tiles(k0, nxt);           // overlap with mma below
        #pragma unroll
        for (int ks = 0; ks < 2; ks++) {           // two k=8 steps per tile
            const int kb = ks * 8;
            unsigned a[MI][4], b[4][2];
            #pragma unroll
            for (int mi = 0; mi < MI; mi++) {
                int row = wm0 + mi*16 + gid;
                a[mi][0] = As[cur][row    ][kb + tg];
                a[mi][1] = As[cur][row + 8][kb + tg];
                a[mi][2] = As[cur][row    ][kb + tg + 4];
                a[mi][3] = As[cur][row + 8][kb + tg + 4];
            }
            #pragma unroll
            for (int ni = 0; ni < 4; ni++) {
                int col = wn0 + ni*8 + gid;
                b[ni][0] = Bs[cur][col][kb + tg];
                b[ni][1] = Bs[cur][col][kb + tg + 4];
            }
            #pragma unroll
            for (int mi = 0; mi < MI; mi++)
                #pragma unroll
                for (int ni = 0; ni < 4; ni++)
                    mma_tf32(acc[mi][ni], a[mi], b[ni]);
        }
        __syncthreads();
        cur = nxt;
    }

    // epilogue: c0:(g,2tg) c1:(g,2tg+1) c2:(g+8,2tg) c3:(g+8,2tg+1)
    #pragma unroll
    for (int mi = 0; mi < MI; mi++) {
        int r0 = m0 + wm0 + mi*16 + gid;
        int r1 = r0 + 8;
        #pragma unroll
        for (int ni = 0; ni < 4; ni++) {
            int c0 = n0 + wn0 + ni*8 + tg*2;
            float v00 = acc[mi][ni][0], v01 = acc[mi][ni][1];
            float v10 = acc[mi][ni][2], v11 = acc[mi][ni][3];
            if (bias) {
                float2 bv = *reinterpret_cast<const float2*>(bias + c0);
                v00 += bv.x; v01 += bv.y; v10 += bv.x; v11 += bv.y;
            }
            if (D) {
                float2 d0 = *reinterpret_cast<const float2*>(D + (size_t)r0*ldd + c0);
                float2 d1 = *reinterpret_cast<const float2*>(D + (size_t)r1*ldd + c0);
                v00 += d0.x; v01 += d0.y; v10 += d1.x; v11 += d1.y;
            }
            size_t o0 = (size_t)r0*ldc + c0;
            size_t o1 = (size_t)r1*ldc + c0;
            if (accum) {
                float2 p0 = *reinterpret_cast<const float2*>(C + o0);
                float2 p1 = *reinterpret_cast<const float2*>(C + o1);
                v00 += p0.x; v01 += p0.y; v10 += p1.x; v11 += p1.y;
            }
            *reinterpret_cast<float2*>(C + o0) = make_float2(v00, v01);
            *reinterpret_cast<float2*>(C + o1) = make_float2(v10, v11);
        }
    }
}

// ---------------- 32x32 tiled transpose: dst[n][k] = src[k][n] ----------------
// src: [rows, cols]; dst: [cols, rows]. block (32,8), grid (cols/32, rows/32).
__global__ void transpose_k(const float* __restrict__ src, float* __restrict__ dst,
                            int rows, int cols) {
    __shared__ float tile[32][33];
    int x = blockIdx.x*32 + threadIdx.x;
    int y0 = blockIdx.y*32;
    #pragma unroll
    for (int j = 0; j < 32; j += 8)
        tile[threadIdx.y + j][threadIdx.x] = src[(size_t)(y0 + threadIdx.y + j)*cols + x];
    __syncthreads();
    int xo = blockIdx.y*32 + threadIdx.x;
    int yo0 = blockIdx.x*32;
    #pragma unroll
    for (int j = 0; j < 32; j += 8)
        dst[(size_t)(yo0 + threadIdx.y + j)*rows + xo] = tile[threadIdx.x][threadIdx.y + j];
}

// ---------------- block reduce ----------------
__device__ __forceinline__ float blockReduceSum(float v) {
    __shared__ float sred[32];
    __syncthreads();
    int lane = threadIdx.x & 31, w = threadIdx.x >> 5;
    #pragma unroll
    for (int o = 16; o > 0; o >>= 1) v += __shfl_down_sync(0xffffffffu, v, o);
    if (lane == 0) sred[w] = v;
    __syncthreads();
    int nw = blockDim.x >> 5;
    v = (threadIdx.x < nw) ? sred[threadIdx.x] : 0.f;
    if (w == 0) {
        #pragma unroll
        for (int o = 16; o > 0; o >>= 1) v += __shfl_down_sync(0xffffffffu, v, o);
        if (lane == 0) sred[0] = v;
    }
    __syncthreads();
    return sred[0];
}

// ---------------- LayerNorm (weight only, eps=1e-5), 256 threads, H=1024 ----------------
__global__ void ln_k(const float* __restrict__ in, const float* __restrict__ w,
                     float* __restrict__ out) {
    size_t row = blockIdx.x;
    float4 x = reinterpret_cast<const float4*>(in + row*HSZ)[threadIdx.x];
    float s = x.x + x.y + x.z + x.w;
    s = blockReduceSum(s);
    float mu = s * (1.f/HSZ);
    float dx = x.x-mu, dy = x.y-mu, dz = x.z-mu, dw = x.w-mu;
    float vs = dx*dx + dy*dy + dz*dz + dw*dw;
    vs = blockReduceSum(vs);
    float r = rsqrtf(vs*(1.f/HSZ) + 1e-5f);
    float4 wv = reinterpret_cast<const float4*>(w)[threadIdx.x];
    float4 o = make_float4(dx*r*wv.x, dy*r*wv.y, dz*r*wv.z, dw*r*wv.w);
    reinterpret_cast<float4*>(out + row*HSZ)[threadIdx.x] = o;
}

// h += LN(ys) * w
__global__ void add_ln_k(const float* __restrict__ ys, const float* __restrict__ w,
                         float* __restrict__ h) {
    size_t row = blockIdx.x;
    float4 x = reinterpret_cast<const float4*>(ys + row*HSZ)[threadIdx.x];
    float s = x.x + x.y + x.z + x.w;
    s = blockReduceSum(s);
    float mu = s * (1.f/HSZ);
    float dx = x.x-mu, dy = x.y-mu, dz = x.z-mu, dw = x.w-mu;
    float vs = dx*dx + dy*dy + dz*dz + dw*dw;
    vs = blockReduceSum(vs);
    float r = rsqrtf(vs*(1.f/HSZ) + 1e-5f);
    float4 wv = reinterpret_cast<const float4*>(w)[threadIdx.x];
    float4 hv = reinterpret_cast<float4*>(h + row*HSZ)[threadIdx.x];
    hv.x += dx*r*wv.x; hv.y += dy*r*wv.y; hv.z += dz*r*wv.z; hv.w += dw*r*wv.w;
    reinterpret_cast<float4*>(h + row*HSZ)[threadIdx.x] = hv;
}

// ---------------- depthwise causal conv (K=4) + SiLU ----------------
__global__ void conv_silu_k(const float* __restrict__ xn, const float* __restrict__ cw,
                            const float* __restrict__ cb, float* __restrict__ xc) {
    size_t idx = (size_t)blockIdx.x*blockDim.x + threadIdx.x;   // < MR*H
    int h = (int)(idx % HSZ);
    size_t bs = idx / HSZ;
    int s = (int)(bs % SSZ);
    float acc = cb[h];
    #pragma unroll
    for (int k = 0; k < KSZ; k++) {
        int s2 = s - (KSZ-1) + k;
        if (s2 >= 0) {
            ptrdiff_t off = (ptrdiff_t)(s2 - s) * HSZ;
            acc += xn[(ptrdiff_t)idx + off] * cw[h*KSZ + k];
        }
    }
    xc[idx] = acc / (1.f + expf(-acc));   // silu
}

// ---------------- sLSTM gate pointwise step ----------------
// writes y only into ys[:, t, :]; next step's GEMM reads it from there.
__global__ void gate_k(const float* __restrict__ raw, const float* __restrict__ cb,
                       float* __restrict__ Cc,
                       float* __restrict__ Nn, float* __restrict__ Mm,
                       float* __restrict__ ys, int t) {
    int idx = blockIdx.x*blockDim.x + threadIdx.x;   // < B*H
    int b = idx >> 10, h = idx & 1023;
    const float* rr = raw + (size_t)b*G4H;
    float ir  = rr[h]          + cb[h];
    float fr  = rr[HSZ + h]    + cb[HSZ + h];
    float zr  = rr[2*HSZ + h]  + cb[2*HSZ + h];
    float orr = rr[3*HSZ + h]  + cb[3*HSZ + h];
    float m = Mm[idx], c = Cc[idx], n = Nn[idx];
    float ls = (fr >= 0.f) ? -log1pf(expf(-fr)) : (fr - log1pf(expf(fr)));  // log_sigmoid
    float lfm = m + ls;
    float mn = (n == 0.f) ? ir : fmaxf(ir, lfm);
    float ig = expf(ir - mn);
    float fg = expf(lfm - mn);
    float cn = fg*c + ig*tanhf(zr);
    float nn2 = fg*n + ig;
    float yv = (1.f/(1.f + expf(-orr))) * cn / nn2;
    Mm[idx] = mn; Cc[idx] = cn; Nn[idx] = nn2;
    ys[((size_t)b*SSZ + t)*HSZ + h] = yv;
}

__global__ void zero_states_k(float* __restrict__ Y, float* __restrict__ C,
                              float* __restrict__ N, float* __restrict__ M) {
    int idx = blockIdx.x*blockDim.x + threadIdx.x;
    Y[idx] = 0.f; C[idx] = 0.f; N[idx] = 0.f; M[idx] = 0.f;
}

// ---------------- gated GELU (exact) ----------------
__global__ void act_k(const float* __restrict__ ff1, float* __restrict__ ff2) {
    size_t idx = (size_t)blockIdx.x*blockDim.x + threadIdx.x;   // < MR*U
    size_t m = idx / USZ;
    int u = (int)(idx % USZ);
    const float* r = ff1 + m*(2*USZ);
    float g = r[u], v = r[USZ + u];
    float ge = 0.5f * g * (1.f + erff(g * 0.70710678118654752440f));
    ff2[idx] = ge * v;
}

// ---------------- final LN + FC on last position ----------------
__global__ void final_k(const float* __restrict__ hbuf, const float* __restrict__ pw,
                        const float* __restrict__ fw, const float* __restrict__ fb,
                        float* __restrict__ out) {
    __shared__ float sh[HSZ];
    int b = blockIdx.x, tid = threadIdx.x;   // 128 threads
    const float* row = hbuf + ((size_t)b*SSZ + SSZ - 1)*HSZ;
    float lv[8];
    float s = 0.f;
    #pragma unroll
    for (int i = 0; i < 8; i++) { lv[i] = row[tid*8 + i]; s += lv[i]; }
    s = blockReduceSum(s);
    float mu = s * (1.f/HSZ);
    float vs = 0.f;
    #pragma unroll
    for (int i = 0; i < 8; i++) { lv[i] -= mu; vs += lv[i]*lv[i]; }
    vs = blockReduceSum(vs);
    float r = rsqrtf(vs*(1.f/HSZ) + 1e-5f);
    #pragma unroll
    for (int i = 0; i < 8; i++) sh[tid*8 + i] = lv[i]*r*pw[tid*8 + i];
    __syncthreads();
    float acc = fb[tid];
    const float* wrow = fw + (size_t)tid*HSZ;
    #pragma unroll 4
    for (int k = 0; k < HSZ; k += 4) {
        float4 wv = *reinterpret_cast<const float4*>(wrow + k);
        acc += sh[k]*wv.x + sh[k+1]*wv.y + sh[k+2]*wv.z + sh[k+3]*wv.w;
    }
    out[b*OSZ + tid] = acc;
}

// ---------------- host ----------------
template <typename T>
static float* sym_addr(const T& sym) {
    void* p = nullptr;
    cudaGetSymbolAddress(&p, sym);
    return (float*)p;
}

extern "C" void kernel_launch(void* const* d_in, const int* in_sizes, int n_in,
                              void* d_out, int out_size) {
    (void)in_sizes; (void)n_in; (void)out_size;
    const float* x      = (const float*)d_in[0];
    const float* emb_w  = (const float*)d_in[1];
    const float* emb_b  = (const float*)d_in[2];
    const float* conv_w = (const float*)d_in[3];
    const float* conv_b = (const float*)d_in[4];
    const float* Wi     = (const float*)d_in[5];
    const float* Wf     = (const float*)d_in[6];
    const float* Wz     = (const float*)d_in[7];
    const float* Wo     = (const float*)d_in[8];
    const float* R      = (const float*)d_in[9];
    const float* cell_b = (const float*)d_in[10];
    const float* gn_w   = (const float*)d_in[11];
    const float* ln1_w  = (const float*)d_in[12];
    const float* ln2_w  = (const float*)d_in[13];
    const float* ff_up  = (const float*)d_in[14];
    const float* ff_down= (const float*)d_in[15];
    const float* post_w = (const float*)d_in[16];
    const float* fc_w   = (const float*)d_in[17];
    const float* fc_b   = (const float*)d_in[18];
    float* out = (float*)d_out;

    float* h   = sym_addr(g_h);
    float* xn  = sym_addr(g_xn);
    float* xc  = sym_addr(g_xc);
    float* ys  = sym_addr(g_ys);
    float* wx  = sym_addr(g_wx);
    float* ff1 = sym_addr(g_ff1);
    float* ff2 = sym_addr(g_ff2);
    float* raw = sym_addr(g_raw);
    float* RT  = sym_addr(g_RT);
    float* Yp  = sym_addr(g_Y);
    float* Cp  = sym_addr(g_C);
    float* Np  = sym_addr(g_N);
    float* Mp  = sym_addr(g_M);

    // h = x @ emb_w.T + emb_b   [25600,128]x[1024,128]^T
    tgemm<4><<<dim3(HSZ/TG_BN, MR/128), 256>>>(
        x, emb_w, h, ISZ, ISZ, ISZ, HSZ, emb_b, nullptr, 0, 0);

    for (int l = 0; l < LSZ; l++) {
        const float* Wl[4] = { Wi + (size_t)l*HSZ*HSZ, Wf + (size_t)l*HSZ*HSZ,
                               Wz + (size_t)l*HSZ*HSZ, Wo + (size_t)l*HSZ*HSZ };
        // xn = LN(h)*ln1_w
        ln_k<<<MR, 256>>>(h, ln1_w + l*HSZ, xn);
        // xc = silu(causal_conv(xn))
        conv_silu_k<<<(MR*HSZ)/256, 256>>>(xn, conv_w + (size_t)l*HSZ*KSZ,
                                           conv_b + l*HSZ, xc);
        // Wx gates: [i,f] from xc, [z,o] from xn
        for (int g = 0; g < 4; g++) {
            const float* Amat = (g < 2) ? xc : xn;
            tgemm<4><<<dim3(HSZ/TG_BN, MR/128), 256>>>(
                Amat, Wl[g], wx + g*HSZ, HSZ, HSZ, HSZ, G4H, nullptr, nullptr, 0, 0);
        }
        // R^T for this layer: R[l] is [H, 4H] -> RT [4H, H]
        transpose_k<<<dim3(G4H/32, HSZ/32), dim3(32, 8)>>>(
            R + (size_t)l*HSZ*G4H, RT, HSZ, G4H);
        // recurrence
        zero_states_k<<<(BSZ*HSZ)/256, 256>>>(Yp, Cp, Np, Mp);
        const float* cbl = cell_b + l*G4H;
        for (int t = 0; t < SSZ; t++) {
            // raw = y_{t-1} @ R + Wx[:,t,:]   (NT against RT, BM=64 -> 128 CTAs)
            const float* At  = (t == 0) ? Yp : (ys + (size_t)(t-1)*HSZ);
            int lda          = (t == 0) ? HSZ : SSZ*HSZ;
            tgemm<2><<<dim3(G4H/TG_BN, BSZ/64), 256>>>(
                At, RT, raw, HSZ, lda, HSZ, G4H, nullptr,
                wx + (size_t)t*G4H, SSZ*G4H, 0);
            gate_k<<<(BSZ*HSZ)/256, 256>>>(raw, cbl, Cp, Np, Mp, ys, t);
        }
        // h += LN(ys)*gn_w
        add_ln_k<<<MR, 256>>>(ys, gn_w + l*HSZ, h);
        // FFN
        ln_k<<<MR, 256>>>(h, ln2_w + l*HSZ, xn);
        tgemm<4><<<dim3((2*USZ)/TG_BN, MR/128), 256>>>(
            xn, ff_up + (size_t)l*2*USZ*HSZ, ff1, HSZ, HSZ, HSZ, 2*USZ,
            nullptr, nullptr, 0, 0);
        act_k<<<((size_t)MR*USZ)/256, 256>>>(ff1, ff2);
        tgemm<4><<<dim3(HSZ/TG_BN, MR/128), 256>>>(
            ff2, ff_down + (size_t)l*HSZ*USZ, h, USZ, USZ, USZ, HSZ,
            nullptr, nullptr, 0, 1);
    }
    final_k<<<BSZ, 128>>>(h, post_w, fc_w, fc_b, out);
}